// round 4
// baseline (speedup 1.0000x reference)
#include <cuda_runtime.h>
#include <cuda_bf16.h>
#include <cstdint>

#define BB 1024
#define SS 512
#define TT 48
#define FULL 0xFFFFFFFFu
#define RING 16
#define LEAD (RING - 2)   // 14 steps of prefetch lead

typedef unsigned long long ull;

__device__ double g_scratch[BB];
__device__ unsigned int g_count = 0;

__device__ __forceinline__ ull pack2f(float a, float b) {
    ull r;
    asm("mov.b64 %0, {%1, %2};" : "=l"(r) : "f"(a), "f"(b));
    return r;
}
__device__ __forceinline__ void unpack2f(ull v, float& lo, float& hi) {
    asm("mov.b64 {%0, %1}, %2;" : "=f"(lo), "=f"(hi) : "l"(v));
}
__device__ __forceinline__ void fma2(ull& acc, ull a, ull b) {
    asm("fma.rn.f32x2 %0, %1, %2, %0;" : "+l"(acc) : "l"(a), "l"(b));
}
__device__ __forceinline__ ull add2(ull a, ull b) {
    ull r;
    asm("add.rn.f32x2 %0, %1, %2;" : "=l"(r) : "l"(a), "l"(b));
    return r;
}
__device__ __forceinline__ float hsum2(ull a, ull b) {
    ull u = add2(a, b);
    float lo, hi;
    unpack2f(u, lo, hi);
    return lo + hi;
}
__device__ __forceinline__ float warp_sum_f(float v) {
    #pragma unroll
    for (int o = 16; o; o >>= 1) v += __shfl_xor_sync(FULL, v, o);
    return v;
}

// One warp (one block) per batch.
// Column mapping: lane l owns columns j, j+16, j+32 with j = l & 15 — all 48
// tags covered. Row split: lanes 0..15 sum rows 0..23, lanes 16..31 rows
// 24..47; halves combined with one shfl.xor(16) per column (both halves then
// hold identical state). E = exp(transitions) in registers, f32x2-packed
// along rows. Product-domain recurrence: p' = (p . E) * exp(em).
// Emissions staged through a 16-step cp.async shared-memory ring.
extern "C" __global__ void __launch_bounds__(32)
crf_kernel(const float* __restrict__ em,      // [B,S,T]
           const int*   __restrict__ tags,    // [B,S]
           const float* __restrict__ mask,    // [B,S]
           const float* __restrict__ trans,   // [T,T]
           const float* __restrict__ startt,  // [T]
           const float* __restrict__ endt,    // [T]
           float* __restrict__ out)
{
    const int lane = threadIdx.x;
    const int b    = blockIdx.x;

    __shared__ __align__(16) float em_s[RING][TT];   // 192B row stride
    __shared__ __align__(16) float p_buf[2][64];

    const int j     = lane & 15;
    const int cA    = j;
    const int cB    = j + 16;
    const int cC    = j + 32;
    const int rbase = (lane < 16) ? 0 : 24;   // row half owned by this lane

    // ---- sequence length (mask is a monotone prefix of ones) ----
    float msum = 0.f;
    #pragma unroll
    for (int k = 0; k < SS / 32; k++) msum += mask[b * SS + k * 32 + lane];
    const int len = __float2int_rn(warp_sum_f(msum));

    // ---- gold path score ----
    float g = 0.f;
    const int  tagbase = b * SS;
    const long embase  = (long)b * SS * TT;
    #pragma unroll 4
    for (int it = 0; it < SS / 32; it++) {
        int t = lane + it * 32;
        if (t < len) {
            int tg = tags[tagbase + t];
            if (t == 0) {
                g += __ldg(&startt[tg]) + __ldg(&em[embase + tg]);
            } else {
                int tp = tags[tagbase + t - 1];
                g += __ldg(&trans[tg * TT + tp]) + __ldg(&em[embase + (long)t * TT + tg]);
            }
            if (t == len - 1) g += __ldg(&endt[tg]);
        }
    }
    const float gold = warp_sum_f(g);

    // ---- E = exp(transitions): this lane's row half for its 3 columns ----
    ull EA[12], EB[12], EC[12];
    #pragma unroll
    for (int k = 0; k < 12; k++) {
        int r = rbase + 2 * k;
        EA[k] = pack2f(__expf(__ldg(&trans[r * TT + cA])),
                       __expf(__ldg(&trans[(r + 1) * TT + cA])));
        EB[k] = pack2f(__expf(__ldg(&trans[r * TT + cB])),
                       __expf(__ldg(&trans[(r + 1) * TT + cB])));
        EC[k] = pack2f(__expf(__ldg(&trans[r * TT + cC])),
                       __expf(__ldg(&trans[(r + 1) * TT + cC])));
    }

    const float* emp = em + embase;

    // ---- init at t = 0 (product domain, shifted by column-0 score) ----
    float sA = __ldg(&startt[cA]) + emp[cA];
    float sB = __ldg(&startt[cB]) + emp[cB];
    float sC = __ldg(&startt[cC]) + emp[cC];
    const float sref = __shfl_sync(FULL, sA, 0);   // column 0's score
    double M = (double)sref;
    float pA = __expf(sA - sref);
    float pB = __expf(sB - sref);
    float pC = __expf(sC - sref);

    const unsigned emsb  = (unsigned)__cvta_generic_to_shared(&em_s[0][0]);
    const unsigned pbase = (unsigned)__cvta_generic_to_shared(&p_buf[0][0]);

    // ---- cp.async prologue: prefetch emission rows for steps 1..LEAD ----
    #pragma unroll
    for (int s = 1; s <= LEAD; s++) {
        if (lane < 12 && s < len) {
            unsigned dst = emsb + (unsigned)((s & (RING - 1)) * 192 + lane * 16);
            const float* src = emp + (long)s * TT + lane * 4;
            asm volatile("cp.async.cg.shared.global [%0], [%1], 16;"
                         :: "r"(dst), "l"(src));
        }
        asm volatile("cp.async.commit_group;");
    }

    // ---- forward recurrence ----
    #pragma unroll 2
    for (int t = 1; t < len; t++) {
        // prefetch emission row for step t + LEAD
        {
            int s = t + LEAD;
            if (lane < 12 && s < len) {
                unsigned dst = emsb + (unsigned)((s & (RING - 1)) * 192 + lane * 16);
                const float* src = emp + (long)s * TT + lane * 4;
                asm volatile("cp.async.cg.shared.global [%0], [%1], 16;"
                             :: "r"(dst), "l"(src));
            }
            asm volatile("cp.async.commit_group;");
        }

        // publish current state (lanes 0..15 carry the full 48-state copy)
        const unsigned pa = pbase + (unsigned)((t & 1) * 256);
        if (lane < 16) {
            asm volatile("st.shared.f32 [%0], %1;" :: "r"(pa + cA * 4), "f"(pA));
            asm volatile("st.shared.f32 [%0], %1;" :: "r"(pa + cB * 4), "f"(pB));
            asm volatile("st.shared.f32 [%0], %1;" :: "r"(pa + cC * 4), "f"(pC));
        }
        asm volatile("cp.async.wait_group 14;");
        __syncwarp();

        // emission exps for step t (off the matvec dependency chain)
        const unsigned ea = emsb + (unsigned)((t & (RING - 1)) * 192);
        float e0, e1, e2;
        asm("ld.shared.f32 %0, [%1];" : "=f"(e0) : "r"(ea + cA * 4));
        asm("ld.shared.f32 %0, [%1];" : "=f"(e1) : "r"(ea + cB * 4));
        asm("ld.shared.f32 %0, [%1];" : "=f"(e2) : "r"(ea + cC * 4));
        float ceA = __expf(e0);
        float ceB = __expf(e1);
        float ceC = __expf(e2);

        // periodic rescale folded into the emission factor (reference is the
        // previous state's column 0 -> off the critical path)
        if ((t & 3) == 0) {
            float ref = __shfl_sync(FULL, pA, 0);
            float inv = __fdividef(1.f, ref);
            ceA *= inv;
            ceB *= inv;
            ceC *= inv;
            M += (double)__logf(ref);
        }

        // half-row matvec: q_c = sum_{i in half} p_i * E_ic
        ull a0 = 0ull, a1 = 0ull, b0 = 0ull, b1 = 0ull, c0 = 0ull, c1 = 0ull;
        const unsigned base = pa + (unsigned)(rbase * 4);
        #pragma unroll
        for (int c = 0; c < 3; c++) {
            ull pP, pQ, pR, pS;
            asm("ld.shared.v2.u64 {%0, %1}, [%2];"
                : "=l"(pP), "=l"(pQ) : "r"(base + c * 32));
            asm("ld.shared.v2.u64 {%0, %1}, [%2];"
                : "=l"(pR), "=l"(pS) : "r"(base + c * 32 + 16));
            fma2(a0, pP, EA[4 * c    ]); fma2(b0, pP, EB[4 * c    ]); fma2(c0, pP, EC[4 * c    ]);
            fma2(a1, pQ, EA[4 * c + 1]); fma2(b1, pQ, EB[4 * c + 1]); fma2(c1, pQ, EC[4 * c + 1]);
            fma2(a0, pR, EA[4 * c + 2]); fma2(b0, pR, EB[4 * c + 2]); fma2(c0, pR, EC[4 * c + 2]);
            fma2(a1, pS, EA[4 * c + 3]); fma2(b1, pS, EB[4 * c + 3]); fma2(c1, pS, EC[4 * c + 3]);
        }
        float qA = hsum2(a0, a1);
        float qB = hsum2(b0, b1);
        float qC = hsum2(c0, c1);
        qA += __shfl_xor_sync(FULL, qA, 16);   // combine row halves
        qB += __shfl_xor_sync(FULL, qB, 16);
        qC += __shfl_xor_sync(FULL, qC, 16);

        pA = qA * ceA;
        pB = qB * ceB;
        pC = qC * ceC;
    }
    asm volatile("cp.async.wait_group 0;" ::: "memory");

    // ---- final: fwd = M + log(sum_c p_c * exp(end_c)) ----
    float v = 0.f;
    if (lane < 16)
        v = pA * __expf(__ldg(&endt[cA]))
          + pB * __expf(__ldg(&endt[cB]))
          + pC * __expf(__ldg(&endt[cC]));
    const float ssum = warp_sum_f(v);
    if (lane == 0)
        g_scratch[b] = M + (double)__logf(ssum) - (double)gold;

    // ---- fused mean: last block reduces ----
    unsigned r = 0;
    if (lane == 0) {
        __threadfence();
        r = atomicAdd(&g_count, 1u);
    }
    r = __shfl_sync(FULL, r, 0);
    if (r == gridDim.x - 1) {
        __threadfence();
        double s = 0.0;
        for (int i = lane; i < BB; i += 32) s += g_scratch[i];
        #pragma unroll
        for (int o = 16; o; o >>= 1) s += __shfl_xor_sync(FULL, s, o);
        if (lane == 0) {
            out[0] = (float)(s / (double)BB);
            g_count = 0;   // reset for next graph replay
        }
    }
}

extern "C" void kernel_launch(void* const* d_in, const int* in_sizes, int n_in,
                              void* d_out, int out_size) {
    const float* em     = (const float*)d_in[0];
    const int*   tags   = (const int*)d_in[1];
    const float* mask   = (const float*)d_in[2];
    const float* trans  = (const float*)d_in[3];
    const float* startt = (const float*)d_in[4];
    const float* endt   = (const float*)d_in[5];
    float* out = (float*)d_out;

    crf_kernel<<<BB, 32>>>(em, tags, mask, trans, startt, endt, out);
}

// round 5
// speedup vs baseline: 1.0501x; 1.0501x over previous
#include <cuda_runtime.h>
#include <cuda_bf16.h>
#include <cstdint>

#define BB 1024
#define SS 512
#define TT 48
#define FULL 0xFFFFFFFFu
#define RING 16
#define LEAD (RING - 2)   // 14 steps of prefetch lead

typedef unsigned long long ull;

__device__ double g_scratch[BB];
__device__ unsigned int g_count = 0;

__device__ __forceinline__ ull pack2f(float a, float b) {
    ull r;
    asm("mov.b64 %0, {%1, %2};" : "=l"(r) : "f"(a), "f"(b));
    return r;
}
__device__ __forceinline__ void unpack2f(ull v, float& lo, float& hi) {
    asm("mov.b64 {%0, %1}, %2;" : "=f"(lo), "=f"(hi) : "l"(v));
}
__device__ __forceinline__ void fma2(ull& acc, ull a, ull b) {
    asm("fma.rn.f32x2 %0, %1, %2, %0;" : "+l"(acc) : "l"(a), "l"(b));
}
__device__ __forceinline__ ull add2(ull a, ull b) {
    ull r;
    asm("add.rn.f32x2 %0, %1, %2;" : "=l"(r) : "l"(a), "l"(b));
    return r;
}
__device__ __forceinline__ float hsum2(ull a, ull b) {
    ull u = add2(a, b);
    float lo, hi;
    unpack2f(u, lo, hi);
    return lo + hi;
}
__device__ __forceinline__ float warp_sum_f(float v) {
    #pragma unroll
    for (int o = 16; o; o >>= 1) v += __shfl_xor_sync(FULL, v, o);
    return v;
}
// Predicated cp.async: no BSSY/BSYNC divergence cost.
__device__ __forceinline__ void cp_async16_pred(unsigned dst, const float* src, int go) {
    asm volatile(
        "{\n\t.reg .pred p;\n\t"
        "setp.ne.b32 p, %0, 0;\n\t"
        "@p cp.async.cg.shared.global [%1], [%2], 16;\n\t}"
        :: "r"(go), "r"(dst), "l"(src));
}

// One warp (one block) per batch.
// Column mapping: lane l owns columns j, j+16, j+32 (j = l & 15).
// Row split: half h = l>>4 sums rows 24h..24h+23. Each lane publishes its
// *partial* q*ce to its half's smem buffer; the next step loads both halves
// and fuses the combine into the matvec front (12 add.f32x2). No shfl and
// no divergent branch anywhere in the step body.
// E = exp(transitions) in registers, f32x2-packed along rows.
// Product domain: p' = (p . E) * exp(em); rescale every 4 steps via smem-read
// reference (off the critical path), shift accumulated in double M.
// Emissions staged through a 16-step cp.async ring.
extern "C" __global__ void __launch_bounds__(32)
crf_kernel(const float* __restrict__ em,      // [B,S,T]
           const int*   __restrict__ tags,    // [B,S]
           const float* __restrict__ mask,    // [B,S]
           const float* __restrict__ trans,   // [T,T]
           const float* __restrict__ startt,  // [T]
           const float* __restrict__ endt,    // [T]
           float* __restrict__ out)
{
    const int lane = threadIdx.x;
    const int b    = blockIdx.x;

    __shared__ __align__(16) float em_s[RING][TT];     // 192B row stride
    __shared__ __align__(16) float p_buf[2][2][80];    // [parity][half][48 + pad]

    const int j     = lane & 15;
    const int cA    = j;
    const int cB    = j + 16;
    const int cC    = j + 32;
    const int half  = lane >> 4;
    const int rbase = half * 24;

    // ---- sequence length (mask is a monotone prefix of ones) ----
    float msum = 0.f;
    #pragma unroll
    for (int k = 0; k < SS / 32; k++) msum += mask[b * SS + k * 32 + lane];
    const int len = __float2int_rn(warp_sum_f(msum));

    // ---- gold path score ----
    float g = 0.f;
    const int  tagbase = b * SS;
    const long embase  = (long)b * SS * TT;
    #pragma unroll 4
    for (int it = 0; it < SS / 32; it++) {
        int t = lane + it * 32;
        if (t < len) {
            int tg = tags[tagbase + t];
            if (t == 0) {
                g += __ldg(&startt[tg]) + __ldg(&em[embase + tg]);
            } else {
                int tp = tags[tagbase + t - 1];
                g += __ldg(&trans[tg * TT + tp]) + __ldg(&em[embase + (long)t * TT + tg]);
            }
            if (t == len - 1) g += __ldg(&endt[tg]);
        }
    }
    const float gold = warp_sum_f(g);

    // ---- E = exp(transitions): this lane's 24 rows for its 3 columns ----
    ull EA[12], EB[12], EC[12];
    #pragma unroll
    for (int k = 0; k < 12; k++) {
        int r = rbase + 2 * k;
        EA[k] = pack2f(__expf(__ldg(&trans[r * TT + cA])),
                       __expf(__ldg(&trans[(r + 1) * TT + cA])));
        EB[k] = pack2f(__expf(__ldg(&trans[r * TT + cB])),
                       __expf(__ldg(&trans[(r + 1) * TT + cB])));
        EC[k] = pack2f(__expf(__ldg(&trans[r * TT + cC])),
                       __expf(__ldg(&trans[(r + 1) * TT + cC])));
    }

    const float* emp = em + embase;

    const unsigned emsb  = (unsigned)__cvta_generic_to_shared(&em_s[0][0]);
    const unsigned pbase = (unsigned)__cvta_generic_to_shared(&p_buf[0][0][0]);
    // this lane's store slots within a parity buffer
    const unsigned stoff = (unsigned)(half * 320 + j * 4);

    // ---- init at t = 0 (product domain, shifted by column-0 score) ----
    {
        float sA = __ldg(&startt[cA]) + emp[cA];
        float sB = __ldg(&startt[cB]) + emp[cB];
        float sC = __ldg(&startt[cC]) + emp[cC];
        const float sref = __shfl_sync(FULL, sA, 0);
        double M0 = (double)sref;
        // low half carries the full initial state; high half publishes zeros
        float iA = (half == 0) ? __expf(sA - sref) : 0.f;
        float iB = (half == 0) ? __expf(sB - sref) : 0.f;
        float iC = (half == 0) ? __expf(sC - sref) : 0.f;
        unsigned st0 = pbase + stoff;   // parity 0
        asm volatile("st.shared.f32 [%0], %1;" :: "r"(st0),       "f"(iA));
        asm volatile("st.shared.f32 [%0], %1;" :: "r"(st0 + 64),  "f"(iB));
        asm volatile("st.shared.f32 [%0], %1;" :: "r"(st0 + 128), "f"(iC));

        // ---- cp.async prologue: emission rows for steps 1..LEAD ----
        #pragma unroll
        for (int s = 1; s <= LEAD; s++) {
            int go = (lane < 12) & (s < len);
            unsigned dst = emsb + (unsigned)((s & (RING - 1)) * 192 + lane * 16);
            cp_async16_pred(dst, emp + (long)s * TT + lane * 4, go);
            asm volatile("cp.async.commit_group;");
        }

        // registers carry the *partial* state per half (matches smem content)
        float pA = iA, pB = iB, pC = iC;
        double M = M0;

        // ---- forward recurrence (branch-free body; rescale branch uniform) ----
        #pragma unroll 2
        for (int t = 1; t < len; t++) {
            // prefetch emission row for step t + LEAD
            {
                int s  = t + LEAD;
                int go = (lane < 12) & (s < len);
                unsigned dst = emsb + (unsigned)((s & (RING - 1)) * 192 + lane * 16);
                cp_async16_pred(dst, emp + (long)s * TT + lane * 4, go);
                asm volatile("cp.async.commit_group;");
                asm volatile("cp.async.wait_group 14;" ::: "memory");
            }

            const unsigned rb = pbase + (unsigned)(((t - 1) & 1) * 640); // read parity
            const unsigned wb = pbase + (unsigned)((t & 1) * 640);       // write parity

            // emission exps for step t (ring slot ready; off the matvec chain)
            const unsigned ea = emsb + (unsigned)((t & (RING - 1)) * 192);
            float e0, e1, e2;
            asm("ld.shared.f32 %0, [%1];" : "=f"(e0) : "r"(ea + cA * 4));
            asm("ld.shared.f32 %0, [%1];" : "=f"(e1) : "r"(ea + cB * 4));
            asm("ld.shared.f32 %0, [%1];" : "=f"(e2) : "r"(ea + cC * 4));
            float ceA = __expf(e0);
            float ceB = __expf(e1);
            float ceC = __expf(e2);

            // periodic rescale: reference = previous state's column 0
            // (lo + hi partials from smem) — entirely off the critical path
            if ((t & 3) == 0) {
                float r0, r1;
                asm volatile("ld.shared.f32 %0, [%1];" : "=f"(r0) : "r"(rb));
                asm volatile("ld.shared.f32 %0, [%1];" : "=f"(r1) : "r"(rb + 320));
                float ref = r0 + r1;
                float inv = __fdividef(1.f, ref);
                ceA *= inv;
                ceB *= inv;
                ceC *= inv;
                M += (double)__logf(ref);
            }

            // matvec over this lane's 24 rows; combine lo+hi partials inline
            ull a0 = 0ull, a1 = 0ull, b0 = 0ull, b1 = 0ull, c0 = 0ull, c1 = 0ull;
            const unsigned lo = rb + (unsigned)(rbase * 4);
            const unsigned hi = rb + 320u + (unsigned)(rbase * 4);
            #pragma unroll
            for (int c = 0; c < 3; c++) {
                ull P0, P1, P2, P3, Q0, Q1, Q2, Q3;
                asm volatile("ld.shared.v2.u64 {%0, %1}, [%2];"
                    : "=l"(P0), "=l"(P1) : "r"(lo + c * 32));
                asm volatile("ld.shared.v2.u64 {%0, %1}, [%2];"
                    : "=l"(P2), "=l"(P3) : "r"(lo + c * 32 + 16));
                asm volatile("ld.shared.v2.u64 {%0, %1}, [%2];"
                    : "=l"(Q0), "=l"(Q1) : "r"(hi + c * 32));
                asm volatile("ld.shared.v2.u64 {%0, %1}, [%2];"
                    : "=l"(Q2), "=l"(Q3) : "r"(hi + c * 32 + 16));
                ull U0 = add2(P0, Q0);
                ull U1 = add2(P1, Q1);
                ull U2 = add2(P2, Q2);
                ull U3 = add2(P3, Q3);
                fma2(a0, U0, EA[4*c  ]); fma2(b0, U0, EB[4*c  ]); fma2(c0, U0, EC[4*c  ]);
                fma2(a1, U1, EA[4*c+1]); fma2(b1, U1, EB[4*c+1]); fma2(c1, U1, EC[4*c+1]);
                fma2(a0, U2, EA[4*c+2]); fma2(b0, U2, EB[4*c+2]); fma2(c0, U2, EC[4*c+2]);
                fma2(a1, U3, EA[4*c+3]); fma2(b1, U3, EB[4*c+3]); fma2(c1, U3, EC[4*c+3]);
            }
            pA = hsum2(a0, a1) * ceA;   // partial (this half's 24 rows) x ce
            pB = hsum2(b0, b1) * ceB;
            pC = hsum2(c0, c1) * ceC;

            // publish partials for the next step (distinct addresses, no branch)
            const unsigned st = wb + stoff;
            asm volatile("st.shared.f32 [%0], %1;" :: "r"(st),       "f"(pA));
            asm volatile("st.shared.f32 [%0], %1;" :: "r"(st + 64),  "f"(pB));
            asm volatile("st.shared.f32 [%0], %1;" :: "r"(st + 128), "f"(pC));
        }
        asm volatile("cp.async.wait_group 0;" ::: "memory");

        // ---- final: fwd = M + log(sum over all lanes of partials * exp(end)) ----
        float v = pA * __expf(__ldg(&endt[cA]))
                + pB * __expf(__ldg(&endt[cB]))
                + pC * __expf(__ldg(&endt[cC]));
        const float ssum = warp_sum_f(v);
        if (lane == 0)
            g_scratch[b] = M + (double)__logf(ssum) - (double)gold;
    }

    // ---- fused mean: last block reduces ----
    unsigned r = 0;
    if (lane == 0) {
        __threadfence();
        r = atomicAdd(&g_count, 1u);
    }
    r = __shfl_sync(FULL, r, 0);
    if (r == gridDim.x - 1) {
        __threadfence();
        double s = 0.0;
        for (int i = lane; i < BB; i += 32) s += g_scratch[i];
        #pragma unroll
        for (int o = 16; o; o >>= 1) s += __shfl_xor_sync(FULL, s, o);
        if (lane == 0) {
            out[0] = (float)(s / (double)BB);
            g_count = 0;   // reset for next graph replay
        }
    }
}

extern "C" void kernel_launch(void* const* d_in, const int* in_sizes, int n_in,
                              void* d_out, int out_size) {
    const float* em     = (const float*)d_in[0];
    const int*   tags   = (const int*)d_in[1];
    const float* mask   = (const float*)d_in[2];
    const float* trans  = (const float*)d_in[3];
    const float* startt = (const float*)d_in[4];
    const float* endt   = (const float*)d_in[5];
    float* out = (float*)d_out;

    crf_kernel<<<BB, 32>>>(em, tags, mask, trans, startt, endt, out);
}